// round 4
// baseline (speedup 1.0000x reference)
#include <cuda_runtime.h>
#include <cuda_bf16.h>
#include <cstdint>

// LocalDynamicGraph edge features:
//   out[b,n,c,k]    = x[b, idx[b,n,k], c] - x[b,n,c]   for c in [0,64)
//   out[b,n,64+c,k] = x[b,n,c]                          for c in [0,64)
// B=8, N=16384, C=64, K=20. Output (B,N,128,20) fp32 = 1.342 GB, write-bound.
// R3: assemble the full per-point output tile (10240B) in smem in final
// layout, emit via one cp.async.bulk shared->global (TMA bulk store). This
// removes all output STG + transpose LDS wavefronts from the L1/LSU pipe
// (246 -> ~136 wf/CTA vs the 240-cycle DRAM budget), leaving DRAM the sole
// binder.

#define BDIM    8
#define NPTS    16384
#define CH      64
#define KNB     20
#define OUTPP   (2 * CH * KNB)   // 2560 floats per point = 10240 B
#define THREADS 128

__device__ int g_idx_is64;

__global__ void detect_idx_dtype_kernel(const long long* __restrict__ p) {
    // Genuine int64 indices all lie in [0, 16384). int32 data aliased as
    // int64 puts a random nonzero index in the high 32 bits of almost every
    // word. Probe 8 words; false-positive prob ~ 16384^-8.
    int is64 = 1;
    #pragma unroll
    for (int i = 0; i < 8; i++) {
        long long v = p[i];
        if (v < 0 || v >= NPTS) is64 = 0;
    }
    g_idx_is64 = is64;
}

__device__ __forceinline__ uint32_t smem_u32(const void* p) {
    return (uint32_t)__cvta_generic_to_shared(p);
}

// Store 10 floats (one half-row of K) at float-offset c2*20 + half*10.
// half==0: base 16B-aligned -> v4,v4,v2.  half==1: base 8B-aligned -> v2,v4,v4.
__device__ __forceinline__ void sts10(float* base, int half,
                                      const float* v) {
    if (half == 0) {
        *(float4*)(base + 0) = make_float4(v[0], v[1], v[2], v[3]);
        *(float4*)(base + 4) = make_float4(v[4], v[5], v[6], v[7]);
        *(float2*)(base + 8) = make_float2(v[8], v[9]);
    } else {
        *(float2*)(base + 0) = make_float2(v[0], v[1]);
        *(float4*)(base + 2) = make_float4(v[2], v[3], v[4], v[5]);
        *(float4*)(base + 6) = make_float4(v[6], v[7], v[8], v[9]);
    }
}

__global__ __launch_bounds__(THREADS)
void edge_feature_kernel(const float* __restrict__ x,
                         const void* __restrict__ idx_raw,
                         float* __restrict__ out) {
    const int pt = blockIdx.x;            // 0 .. B*N-1
    const int b  = pt >> 14;              // N = 16384
    const int n  = pt & (NPTS - 1);
    const int t  = threadIdx.x;

    __shared__ __align__(16) float s_out[OUTPP];   // final output layout (2C,K)
    __shared__ int s_nidx[24];            // rows 0..9 at [0..9], 10..19 at [12..21]

    const float* xb   = x + (size_t)b * NPTS * CH;
    const float* xrow = xb + (size_t)n * CH;

    // --- stage neighbor indices ---
    if (t < KNB) {
        long long v;
        if (g_idx_is64) v = ((const long long*)idx_raw)[(size_t)pt * KNB + t];
        else            v = (long long)((const int*)idx_raw)[(size_t)pt * KNB + t];
        s_nidx[t < 10 ? t : t + 2] = (int)v;   // 16B-aligned bases per half
    }
    __syncthreads();

    // --- thread owns channel c and 10 consecutive k (rows) ---
    const int c    = t & (CH - 1);        // 0..63
    const int half = t >> 6;              // warps 0,1 -> k 0..9; warps 2,3 -> k 10..19
    const float ctr_c = __ldg(xrow + c);

    const int base = half * 12;
    int4 ra = *(const int4*)&s_nidx[base];
    int4 rb = *(const int4*)&s_nidx[base + 4];
    int2 rc = *(const int2*)&s_nidx[base + 8];
    const int rows[10] = {ra.x, ra.y, ra.z, ra.w, rb.x, rb.y, rb.z, rb.w, rc.x, rc.y};

    // --- issue all gathers (MLP=10, 128B-coalesced per warp, L2 hits) ---
    float g[10];
    #pragma unroll
    for (int i = 0; i < 10; i++)
        g[i] = xb[(size_t)rows[i] * CH + c];

    // --- center-broadcast half: independent of gathers, overlaps LDG latency
    // s_out[(64+c)*20 + half*10 .. +10] = ctr_c
    {
        float cv[10];
        #pragma unroll
        for (int i = 0; i < 10; i++) cv[i] = ctr_c;
        sts10(&s_out[(CH + c) * KNB + half * 10], half, cv);
    }

    // --- edge half: s_out[c*20 + half*10 + i] = g[i] - ctr ---
    {
        float dv[10];
        #pragma unroll
        for (int i = 0; i < 10; i++) dv[i] = g[i] - ctr_c;
        sts10(&s_out[c * KNB + half * 10], half, dv);
    }
    __syncthreads();

    // --- one TMA bulk store: smem tile -> out[pt*2560 ..], 10240 B ---
    if (t == 0) {
        asm volatile("fence.proxy.async.shared::cta;" ::: "memory");
        uint64_t gptr = (uint64_t)(out + (size_t)pt * OUTPP);
        uint32_t sptr = smem_u32(s_out);
        asm volatile(
            "cp.async.bulk.global.shared::cta.bulk_group [%0], [%1], %2;"
            :: "l"(gptr), "r"(sptr), "n"(OUTPP * 4) : "memory");
        asm volatile("cp.async.bulk.commit_group;" ::: "memory");
        // Keep the CTA alive until TMA has read smem.
        asm volatile("cp.async.bulk.wait_group.read 0;" ::: "memory");
    }
}

extern "C" void kernel_launch(void* const* d_in, const int* in_sizes, int n_in,
                              void* d_out, int out_size) {
    const float* x   = (const float*)d_in[0];
    const void*  idx = d_in[1];
    float*       out = (float*)d_out;

    detect_idx_dtype_kernel<<<1, 1>>>((const long long*)idx);
    edge_feature_kernel<<<BDIM * NPTS, THREADS>>>(x, idx, out);
}

// round 5
// speedup vs baseline: 1.0113x; 1.0113x over previous
#include <cuda_runtime.h>
#include <cuda_bf16.h>
#include <cstdint>

// LocalDynamicGraph edge features:
//   out[b,n,c,k]    = x[b, idx[b,n,k], c] - x[b,n,c]   for c in [0,64)
//   out[b,n,64+c,k] = x[b,n,c]                          for c in [0,64)
// B=8, N=16384, C=64, K=20. Output (B,N,128,20) fp32 = 1.342 GB, write-bound.
// R4: split store paths. Center-broadcast half (5KB/pt) = direct coalesced
// STG.128 (no transpose needed). Edge half (5KB/pt) = smem transpose + one
// TMA bulk store. L1/smem port: 210 -> ~170 cyc/CTA vs 240-cyc DRAM budget.

#define BDIM    8
#define NPTS    16384
#define CH      64
#define KNB     20
#define OUTPP   (2 * CH * KNB)   // 2560 floats per point
#define EDGEF   (CH * KNB)       // 1280 floats = 5120 B edge half
#define THREADS 128

__device__ int g_idx_is64;

__global__ void detect_idx_dtype_kernel(const long long* __restrict__ p) {
    // Genuine int64 indices all lie in [0, 16384). int32 data aliased as
    // int64 puts a random nonzero index in the high 32 bits of almost every
    // word. Probe 8 words; false-positive prob ~ 16384^-8.
    int is64 = 1;
    #pragma unroll
    for (int i = 0; i < 8; i++) {
        long long v = p[i];
        if (v < 0 || v >= NPTS) is64 = 0;
    }
    g_idx_is64 = is64;
}

__device__ __forceinline__ uint32_t smem_u32(const void* p) {
    return (uint32_t)__cvta_generic_to_shared(p);
}

// Store 10 floats at float-offset c*20 + half*10.
// half==0: 16B-aligned base -> v4,v4,v2.  half==1: 8B-aligned -> v2,v4,v4.
__device__ __forceinline__ void sts10(float* base, int half, const float* v) {
    if (half == 0) {
        *(float4*)(base + 0) = make_float4(v[0], v[1], v[2], v[3]);
        *(float4*)(base + 4) = make_float4(v[4], v[5], v[6], v[7]);
        *(float2*)(base + 8) = make_float2(v[8], v[9]);
    } else {
        *(float2*)(base + 0) = make_float2(v[0], v[1]);
        *(float4*)(base + 2) = make_float4(v[2], v[3], v[4], v[5]);
        *(float4*)(base + 6) = make_float4(v[6], v[7], v[8], v[9]);
    }
}

__global__ __launch_bounds__(THREADS)
void edge_feature_kernel(const float* __restrict__ x,
                         const void* __restrict__ idx_raw,
                         float* __restrict__ out) {
    const int pt = blockIdx.x;            // 0 .. B*N-1
    const int b  = pt >> 14;              // N = 16384
    const int n  = pt & (NPTS - 1);
    const int t  = threadIdx.x;

    __shared__ __align__(16) float s_edge[EDGEF];   // (C,K) edge half, final layout
    __shared__ int s_nidx[24];            // rows 0..9 at [0..9], 10..19 at [12..21]

    const float* xb   = x + (size_t)b * NPTS * CH;
    const float* xrow = xb + (size_t)n * CH;
    float* outpt = out + (size_t)pt * OUTPP;

    // --- stage neighbor indices ---
    if (t < KNB) {
        long long v;
        if (g_idx_is64) v = ((const long long*)idx_raw)[(size_t)pt * KNB + t];
        else            v = (long long)((const int*)idx_raw)[(size_t)pt * KNB + t];
        s_nidx[t < 10 ? t : t + 2] = (int)v;   // 16B-aligned bases per half
    }
    __syncthreads();

    // --- thread owns channel c, 10 consecutive k ---
    const int c    = t & (CH - 1);        // 0..63
    const int half = t >> 6;              // warps 0,1 -> k 0..9; 2,3 -> k 10..19
    const float ctr_c = __ldg(xrow + c);

    const int base = half * 12;
    int4 ra = *(const int4*)&s_nidx[base];
    int4 rb = *(const int4*)&s_nidx[base + 4];
    int2 rc = *(const int2*)&s_nidx[base + 8];
    const int rows[10] = {ra.x, ra.y, ra.z, ra.w, rb.x, rb.y, rb.z, rb.w, rc.x, rc.y};

    // --- issue all gathers (MLP=10, coalesced, L2 hits) ---
    float g[10];
    #pragma unroll
    for (int i = 0; i < 10; i++)
        g[i] = xb[(size_t)rows[i] * CH + c];

    // --- center-broadcast half: DIRECT coalesced STG, overlaps gather latency.
    // out floats [1280,2560): value = xrow[(1280 + j4*4)/20 - 64] = xrow[j4/5].
    float4* bc = (float4*)(outpt + EDGEF);
    #pragma unroll
    for (int i = 0; i < 3; i++) {
        const int j4 = t + i * THREADS;   // 0..383, need < 320
        if (j4 < 320) {
            const float ctr = __ldg(xrow + j4 / 5);   // L1-hit broadcast
            __stcs(&bc[j4], make_float4(ctr, ctr, ctr, ctr));
        }
    }

    // --- edge half into smem (pre-subtracted, final layout) ---
    {
        float dv[10];
        #pragma unroll
        for (int i = 0; i < 10; i++) dv[i] = g[i] - ctr_c;
        sts10(&s_edge[c * KNB + half * 10], half, dv);
    }
    __syncthreads();

    // --- one TMA bulk store: 5120 B edge tile -> out[pt*2560 ..] ---
    if (t == 0) {
        asm volatile("fence.proxy.async.shared::cta;" ::: "memory");
        uint64_t gptr = (uint64_t)outpt;
        uint32_t sptr = smem_u32(s_edge);
        asm volatile(
            "cp.async.bulk.global.shared::cta.bulk_group [%0], [%1], %2;"
            :: "l"(gptr), "r"(sptr), "n"(EDGEF * 4) : "memory");
        asm volatile("cp.async.bulk.commit_group;" ::: "memory");
        asm volatile("cp.async.bulk.wait_group.read 0;" ::: "memory");
    }
}

extern "C" void kernel_launch(void* const* d_in, const int* in_sizes, int n_in,
                              void* d_out, int out_size) {
    const float* x   = (const float*)d_in[0];
    const void*  idx = d_in[1];
    float*       out = (float*)d_out;

    detect_idx_dtype_kernel<<<1, 1>>>((const long long*)idx);
    edge_feature_kernel<<<BDIM * NPTS, THREADS>>>(x, idx, out);
}